// round 3
// baseline (speedup 1.0000x reference)
#include <cuda_runtime.h>
#include <math.h>

#define N_SAMP 60000
#define N_PAD  60160   // 235*256, zero-padded tail
#define K_BINS 1400
#define NB1    235     // outer-index table size (n1)
#define BT     256     // block threads == inner-index stride (n0)

// Scratch (no allocations allowed)
__device__ float2 g_o[N_PAD];
__device__ float4 g_ri[K_BINS];   // (re1, im1, re2, im2)

// ---------------- packed f32x2 helpers (Blackwell native) ----------------
typedef unsigned long long ull;
__device__ __forceinline__ ull pk(float lo, float hi) {
    ull r; asm("mov.b64 %0,{%1,%2};" : "=l"(r) : "f"(lo), "f"(hi)); return r;
}
__device__ __forceinline__ void upk(ull v, float& lo, float& hi) {
    asm("mov.b64 {%0,%1},%2;" : "=f"(lo), "=f"(hi) : "l"(v));
}
__device__ __forceinline__ ull fma2(ull a, ull b, ull c) {
    ull d; asm("fma.rn.f32x2 %0,%1,%2,%3;" : "=l"(d) : "l"(a), "l"(b), "l"(c)); return d;
}
__device__ __forceinline__ ull mul2(ull a, ull b) {
    ull d; asm("mul.rn.f32x2 %0,%1,%2;" : "=l"(d) : "l"(a), "l"(b)); return d;
}
__device__ __forceinline__ ull add2(ull a, ull b) {
    ull d; asm("add.rn.f32x2 %0,%1,%2;" : "=l"(d) : "l"(a), "l"(b)); return d;
}
__device__ __forceinline__ ull neg2(ull a) {       // 2x LOP on alu pipe
    return a ^ 0x8000000080000000ULL;
}

// ---------------------------------------------------------------------------
// Kernel A: o[n] = signal[n] * hanning[n], interleaved, padded.
// One fp64 sincos per 8-element group + double rotation recurrence;
// Hann symmetry h[i]==h[N-1-i] halves the groups.
// ---------------------------------------------------------------------------
#define HGRP 8
__global__ void prep_kernel(const float* __restrict__ preds,
                            const float* __restrict__ labels) {
    int t = blockIdx.x * blockDim.x + threadIdx.x;
    if (t < (N_PAD - N_SAMP)) g_o[N_SAMP + t] = make_float2(0.f, 0.f);
    int base = t * HGRP;
    if (base >= N_SAMP / 2) return;

    const double PI = 3.141592653589793;
    const double dN1 = (double)(N_SAMP - 1);
    double th  = PI * ((double)(2 * base + 1 - N_SAMP) / dN1);
    double sd, cd, s, c;
    sincos(2.0 * PI / dN1, &sd, &cd);   // step angle
    sincos(th, &s, &c);

#pragma unroll
    for (int q = 0; q < HGRP; q++) {
        int i = base + q;
        float h = (float)(0.5 + 0.5 * c);
        g_o[i] = make_float2(preds[i] * h, labels[i] * h);
        int m = N_SAMP - 1 - i;
        g_o[m] = make_float2(preds[m] * h, labels[m] * h);
        double cn = c * cd - s * sd;    // rotate by step
        s = s * cd + c * sd;
        c = cn;
    }
}

// ---------------------------------------------------------------------------
// Kernel B: TWO bins per block, packed ACROSS bins (lane0 = bin j0,
// lane1 = bin j0+1) so no mid-loop unpack is needed. Reproduces the
// reference's f32 angle rounding exactly (ang = A - D, D = e2 + k*e1 from
// exact FMA residuals), table angle-addition for cos/sin(A), first-order
// rotation by D. 16 f32x2 FMA-pipe ops per iteration for both bins.
// ---------------------------------------------------------------------------
__global__ void __launch_bounds__(BT)
psd_kernel(const float* __restrict__ bpm) {
    const int j0  = blockIdx.x * 2;
    const int tid = threadIdx.x;

    __shared__ float4 tb[NB1];        // (cB_b0, cB_b1, sB_b0, sB_b1)
    __shared__ ull    wsum[8][4];

    const float cF   = (float)(2.0 * 3.141592653589793 / 60000.0);
    const float unit = (float)(30.0 / 60000.0);

    float  kk[2];
    double kc[2];
#pragma unroll
    for (int b = 0; b < 2; b++) {
        kk[b] = __fdiv_rn(__fdiv_rn(bpm[j0 + b], 60.0f), unit);
        kc[b] = (double)kk[b] * (double)cF;        // exact product
    }
    const ull kk2 = pk(kk[0], kk[1]);
    const ull cF2 = pk(cF, cF);

    // Block table: cos/sin(k*c*256*n1) for both bins, fp64 build
    for (int idx = tid; idx < 2 * NB1; idx += BT) {
        int n1 = idx >> 1, b = idx & 1;
        double s, c;
        sincos(kc[b] * (double)(n1 * 256), &s, &c);
        float* p = (float*)&tb[n1];
        p[b]     = (float)c;
        p[2 + b] = (float)s;
    }

    // Per-thread inner factors cos/sin(k*c*tid), packed across bins
    double s0, c0, s1, c1;
    sincos(kc[0] * (double)tid, &s0, &c0);
    sincos(kc[1] * (double)tid, &s1, &c1);
    const ull cS2 = pk((float)c0, (float)c1);
    const ull sS2 = pk((float)s0, (float)s1);

    ull aR1 = 0ULL, aI1 = 0ULL, aR2 = 0ULL, aI2 = 0ULL;
    __syncthreads();

    ull nf2 = pk((float)tid, (float)tid);   // n = 256*n1 + tid (exact in f32)
    const ull st2 = pk(256.f, 256.f);
    const float2* op = g_o + tid;

#pragma unroll 5
    for (int n1 = 0; n1 < NB1; ++n1) {
        float4 t = tb[n1];                       // LDS.128 broadcast
        ull cB2 = pk(t.x, t.y);
        ull sB2 = pk(t.z, t.w);
        // reference rounding chain + exact residuals, packed across bins
        ull tpn2 = mul2(cF2, nf2);               // fl32(c*n)
        ull e1_2 = fma2(cF2, nf2, neg2(tpn2));   // exact residual
        nf2 = add2(nf2, st2);
        ull ang2 = mul2(kk2, tpn2);              // fl32(k*tpn)
        ull e2_2 = fma2(kk2, tpn2, neg2(ang2));  // exact residual
        ull D2   = fma2(kk2, e1_2, e2_2);        // ang = A - D
        // cos/sin of exact A via angle addition
        ull cA2 = fma2(neg2(sB2), sS2, mul2(cB2, cS2));
        ull sA2 = fma2(cB2, sS2, mul2(sB2, cS2));
        // rotate by -D (first order)
        ull cr2 = fma2(D2, sA2, cA2);
        ull sr2 = fma2(neg2(D2), cA2, sA2);
        float2 o = op[n1 * BT];
        ull ox2 = pk(o.x, o.x);
        ull oy2 = pk(o.y, o.y);
        aR1 = fma2(cr2, ox2, aR1);
        aI1 = fma2(sr2, ox2, aI1);
        aR2 = fma2(cr2, oy2, aR2);
        aI2 = fma2(sr2, oy2, aI2);
    }

    // Warp reduction on packed accumulators (halves independent)
    const unsigned msk = 0xFFFFFFFFu;
    for (int off = 16; off; off >>= 1) {
        aR1 = add2(aR1, __shfl_down_sync(msk, aR1, off));
        aI1 = add2(aI1, __shfl_down_sync(msk, aI1, off));
        aR2 = add2(aR2, __shfl_down_sync(msk, aR2, off));
        aI2 = add2(aI2, __shfl_down_sync(msk, aI2, off));
    }
    int w = tid >> 5, lane = tid & 31;
    if (lane == 0) {
        wsum[w][0] = aR1; wsum[w][1] = aI1;
        wsum[w][2] = aR2; wsum[w][3] = aI2;
    }
    __syncthreads();
    if (w == 0) {
        ull v0 = (lane < 8) ? wsum[lane][0] : 0ULL;
        ull v1 = (lane < 8) ? wsum[lane][1] : 0ULL;
        ull v2 = (lane < 8) ? wsum[lane][2] : 0ULL;
        ull v3 = (lane < 8) ? wsum[lane][3] : 0ULL;
        for (int off = 4; off; off >>= 1) {
            v0 = add2(v0, __shfl_down_sync(msk, v0, off));
            v1 = add2(v1, __shfl_down_sync(msk, v1, off));
            v2 = add2(v2, __shfl_down_sync(msk, v2, off));
            v3 = add2(v3, __shfl_down_sync(msk, v3, off));
        }
        if (lane == 0) {
            float r1a, r1b, i1a, i1b, r2a, r2b, i2a, i2b;
            upk(v0, r1a, r1b); upk(v1, i1a, i1b);
            upk(v2, r2a, r2b); upk(v3, i2a, i2b);
            g_ri[j0]     = make_float4(r1a, i1a, r2a, i2a);
            g_ri[j0 + 1] = make_float4(r1b, i1b, r2b, i2b);
        }
    }
}

// ---------------------------------------------------------------------------
// Kernel C: ca = re^2+im^2; pn = ca/max(ca) (sum normalization cancels);
// loss = ||pn1 - pn2||; out = 1/(loss + 1e-8)
// ---------------------------------------------------------------------------
__global__ void __launch_bounds__(256)
final_kernel(float* __restrict__ out) {
    __shared__ float ca1s[K_BINS];
    __shared__ float ca2s[K_BINS];
    __shared__ float redf[64];
    __shared__ double redd[8];
    const int tid = threadIdx.x;
    const int w = tid >> 5, lane = tid & 31;
    const unsigned m = 0xFFFFFFFFu;

    float m1 = 0.f, m2 = 0.f;
    for (int j = tid; j < K_BINS; j += 256) {
        float4 v = g_ri[j];
        float ca1 = __fmaf_rn(v.y, v.y, __fmul_rn(v.x, v.x));
        float ca2 = __fmaf_rn(v.w, v.w, __fmul_rn(v.z, v.z));
        ca1s[j] = ca1; ca2s[j] = ca2;
        m1 = fmaxf(m1, ca1); m2 = fmaxf(m2, ca2);
    }
    for (int off = 16; off; off >>= 1) {
        m1 = fmaxf(m1, __shfl_down_sync(m, m1, off));
        m2 = fmaxf(m2, __shfl_down_sync(m, m2, off));
    }
    if (lane == 0) { redf[w] = m1; redf[32 + w] = m2; }
    __syncthreads();
    if (tid == 0) {
        float a = redf[0], b = redf[32];
        for (int i = 1; i < 8; i++) { a = fmaxf(a, redf[i]); b = fmaxf(b, redf[32 + i]); }
        redf[0] = a; redf[32] = b;
    }
    __syncthreads();
    const float max1 = redf[0], max2 = redf[32];

    double ss = 0.0;
    for (int j = tid; j < K_BINS; j += 256) {
        float p1 = __fdiv_rn(ca1s[j], max1);
        float p2 = __fdiv_rn(ca2s[j], max2);
        double d = (double)p1 - (double)p2;
        ss += d * d;
    }
    for (int off = 16; off; off >>= 1) ss += __shfl_down_sync(m, ss, off);
    if (lane == 0) redd[w] = ss;
    __syncthreads();
    if (tid == 0) {
        double t = 0.0;
        for (int i = 0; i < 8; i++) t += redd[i];
        float loss = (float)sqrt(t);
        out[0] = __fdiv_rn(1.0f, loss + 1e-8f);
    }
}

// ---------------------------------------------------------------------------
// Inputs (metadata order): preds f32[60000], labels f32[60000], Fs i32[1],
//                          bpm_range f32[1400]. Output: f32[1].
// ---------------------------------------------------------------------------
extern "C" void kernel_launch(void* const* d_in, const int* in_sizes, int n_in,
                              void* d_out, int out_size) {
    const float* preds  = (const float*)d_in[0];
    const float* labels = (const float*)d_in[1];
    const float* bpm    = (const float*)d_in[3];

    int prep_threads = (N_SAMP / 2 + HGRP - 1) / HGRP;     // 3750
    prep_kernel<<<(prep_threads + 255) / 256, 256>>>(preds, labels);
    psd_kernel<<<K_BINS / 2, BT>>>(bpm);
    final_kernel<<<1, 256>>>((float*)d_out);
}

// round 4
// speedup vs baseline: 1.0862x; 1.0862x over previous
#include <cuda_runtime.h>
#include <math.h>

#define N_SAMP 60000
#define N_PAD  60160   // 235*256, zero-padded tail
#define K_BINS 1400
#define NB1    235     // outer-index table size (n1)
#define BT     256     // block threads == inner-index stride (n0)

// Scratch (no allocations allowed)
__device__ float2 g_o[N_PAD];
__device__ float4 g_ri[K_BINS];   // (re1, im1, re2, im2)

// ---------------- packed f32x2 helpers (Blackwell native) ----------------
typedef unsigned long long ull;
__device__ __forceinline__ ull pk(float lo, float hi) {
    ull r; asm("mov.b64 %0,{%1,%2};" : "=l"(r) : "f"(lo), "f"(hi)); return r;
}
__device__ __forceinline__ void upk(ull v, float& lo, float& hi) {
    asm("mov.b64 {%0,%1},%2;" : "=f"(lo), "=f"(hi) : "l"(v));
}
__device__ __forceinline__ ull fma2(ull a, ull b, ull c) {
    ull d; asm("fma.rn.f32x2 %0,%1,%2,%3;" : "=l"(d) : "l"(a), "l"(b), "l"(c)); return d;
}
__device__ __forceinline__ ull mul2(ull a, ull b) {
    ull d; asm("mul.rn.f32x2 %0,%1,%2;" : "=l"(d) : "l"(a), "l"(b)); return d;
}
__device__ __forceinline__ float fneg(float x) {   // sign flip on ALU pipe (LOP)
    return __int_as_float(__float_as_int(x) ^ 0x80000000);
}

// ---------------------------------------------------------------------------
// Kernel A (R2-proven): o[n] = signal[n]*hanning[n], interleaved, padded.
// Hann symmetry h[i]==h[N-1-i] halves the fp64 cos count; one cos/thread.
// ---------------------------------------------------------------------------
__global__ void prep_kernel(const float* __restrict__ preds,
                            const float* __restrict__ labels) {
    int i = blockIdx.x * blockDim.x + threadIdx.x;
    if (i < (N_PAD - N_SAMP)) g_o[N_SAMP + i] = make_float2(0.f, 0.f);
    if (i >= N_SAMP / 2) return;
    double t = 3.141592653589793 *
               ((double)(2 * i + 1 - N_SAMP) / (double)(N_SAMP - 1));
    float h = (float)(0.5 + 0.5 * cos(t));
    g_o[i] = make_float2(preds[i] * h, labels[i] * h);
    int m = N_SAMP - 1 - i;
    g_o[m] = make_float2(preds[m] * h, labels[m] * h);
}

// ---------------------------------------------------------------------------
// Kernel B: TWO bins per block (R2-proven main loop). Prologue now builds
// both trig tables two-level: 126 fp64 sincos per block (was 982), with
// f32 angle-addition combines (4 FMA/entry). Reproduces the reference's
// f32 angle rounding exactly (ang = A - D, D = e2 + k*e1 from exact FMA
// residuals); first-order rotation by D.
// ---------------------------------------------------------------------------
__global__ void __launch_bounds__(BT)
psd_kernel(const float* __restrict__ bpm) {
    const int j0  = blockIdx.x * 2;
    const int tid = threadIdx.x;

    __shared__ float4 tb[NB1][2];     // per (n1, bin): (cB, sB, -sB, cB)
    __shared__ float2 subI[2][2][16]; // [bin][hi/lo][e]: inner factors tid=16h+l
    __shared__ float2 subB[2][2][16]; // [bin][hi/lo][e]: tabB n1=16a+b
    __shared__ float4 wsum[8][2];

    const float cF   = (float)(2.0 * 3.141592653589793 / 60000.0);
    const float unit = (float)(30.0 / 60000.0);

    float  kk[2];
    double kc[2];
#pragma unroll
    for (int b = 0; b < 2; b++) {
        kk[b] = __fdiv_rn(__fdiv_rn(bpm[j0 + b], 60.0f), unit);
        kc[b] = (double)kk[b] * (double)cF;        // exact product
    }

    // Phase 1: fp64 sincos subtables (128 evals total, threads 0..127)
    if (tid < 128) {
        int b   = tid & 1;
        int t   = tid >> 1;        // 0..63
        int tbl = t >> 4;          // 0: innerHi, 1: innerLo, 2: BHi, 3: BLo
        int e   = t & 15;
        double mult = (tbl == 0) ? (double)(16 * e)
                    : (tbl == 1) ? (double)e
                    : (tbl == 2) ? (double)(4096 * e)
                                 : (double)(256 * e);
        double s, c;
        sincos(kc[b] * mult, &s, &c);
        float2 v = make_float2((float)c, (float)s);
        if (tbl < 2) subI[b][tbl][e] = v;
        else         subB[b][tbl - 2][e] = v;
    }
    __syncthreads();

    // Phase 2a: build block table via f32 angle addition
    for (int idx = tid; idx < 2 * NB1; idx += BT) {
        int n1 = idx >> 1, b = idx & 1;
        float2 H = subB[b][0][n1 >> 4];
        float2 L = subB[b][1][n1 & 15];
        float cB = __fmaf_rn(-H.y, L.y, __fmul_rn(H.x, L.x));
        float sB = __fmaf_rn( H.x, L.y, __fmul_rn(H.y, L.x));
        tb[n1][b] = make_float4(cB, sB, -sB, cB);
    }

    // Phase 2b: per-thread inner factors via f32 angle addition
    ull cS2[2], sS2[2], acc1[2], acc2[2];
#pragma unroll
    for (int b = 0; b < 2; b++) {
        float2 H = subI[b][0][tid >> 4];
        float2 L = subI[b][1][tid & 15];
        float cf = __fmaf_rn(-H.y, L.y, __fmul_rn(H.x, L.x));
        float sf = __fmaf_rn( H.x, L.y, __fmul_rn(H.y, L.x));
        cS2[b] = pk(cf, cf);
        sS2[b] = pk(sf, sf);
        acc1[b] = 0ULL;
        acc2[b] = 0ULL;
    }
    __syncthreads();

    // Main loop (R2-proven): 19 FMA-pipe issues per 2-bin iteration
    float nf = (float)tid;                 // n = 256*n1 + tid (exact in f32)
    const float2* op = g_o + tid;

#pragma unroll 5
    for (int n1 = 0; n1 < NB1; ++n1) {
        float tpn = __fmul_rn(cF, nf);             // fl32(c*n)
        float e1  = __fmaf_rn(cF, nf, -tpn);       // exact residual
        nf += 256.0f;
        float2 o  = op[n1 * BT];
        ull ox2 = pk(o.x, o.x);
        ull oy2 = pk(o.y, o.y);
#pragma unroll
        for (int b = 0; b < 2; b++) {
            float4 t = tb[n1][b];                  // LDS.128 broadcast
            float ang = __fmul_rn(kk[b], tpn);
            float e2  = __fmaf_rn(kk[b], tpn, -ang);
            float D   = __fmaf_rn(kk[b], e1, e2);  // ang = A - D
            ull cs = fma2(pk(t.z, t.w), sS2[b], mul2(pk(t.x, t.y), cS2[b])); // (cA,sA)
            float cA, sA; upk(cs, cA, sA);
            ull crsr = fma2(pk(D, fneg(D)), pk(sA, cA), cs);  // rotate by -D
            acc1[b] = fma2(crsr, ox2, acc1[b]);    // (re,im) preds
            acc2[b] = fma2(crsr, oy2, acc2[b]);    // (re,im) labels
        }
    }

    // Block reduction (R2-proven)
    float r1[2], i1[2], r2[2], i2[2];
#pragma unroll
    for (int b = 0; b < 2; b++) { upk(acc1[b], r1[b], i1[b]); upk(acc2[b], r2[b], i2[b]); }

    const unsigned msk = 0xFFFFFFFFu;
    for (int off = 16; off; off >>= 1) {
#pragma unroll
        for (int b = 0; b < 2; b++) {
            r1[b] += __shfl_down_sync(msk, r1[b], off);
            i1[b] += __shfl_down_sync(msk, i1[b], off);
            r2[b] += __shfl_down_sync(msk, r2[b], off);
            i2[b] += __shfl_down_sync(msk, i2[b], off);
        }
    }
    int w = tid >> 5, lane = tid & 31;
    if (lane == 0) {
#pragma unroll
        for (int b = 0; b < 2; b++)
            wsum[w][b] = make_float4(r1[b], i1[b], r2[b], i2[b]);
    }
    __syncthreads();
    if (w == 0) {
#pragma unroll
        for (int b = 0; b < 2; b++) {
            float4 v = (lane < 8) ? wsum[lane][b] : make_float4(0.f, 0.f, 0.f, 0.f);
            for (int off = 4; off; off >>= 1) {
                v.x += __shfl_down_sync(msk, v.x, off);
                v.y += __shfl_down_sync(msk, v.y, off);
                v.z += __shfl_down_sync(msk, v.z, off);
                v.w += __shfl_down_sync(msk, v.w, off);
            }
            if (lane == 0) g_ri[j0 + b] = v;
        }
    }
}

// ---------------------------------------------------------------------------
// Kernel C: ca = re^2+im^2; pn = ca/max(ca) (sum normalization cancels);
// loss = ||pn1 - pn2||; out = 1/(loss + 1e-8)
// ---------------------------------------------------------------------------
__global__ void __launch_bounds__(256)
final_kernel(float* __restrict__ out) {
    __shared__ float ca1s[K_BINS];
    __shared__ float ca2s[K_BINS];
    __shared__ float redf[64];
    __shared__ double redd[8];
    const int tid = threadIdx.x;
    const int w = tid >> 5, lane = tid & 31;
    const unsigned m = 0xFFFFFFFFu;

    float m1 = 0.f, m2 = 0.f;
    for (int j = tid; j < K_BINS; j += 256) {
        float4 v = g_ri[j];
        float ca1 = __fmaf_rn(v.y, v.y, __fmul_rn(v.x, v.x));
        float ca2 = __fmaf_rn(v.w, v.w, __fmul_rn(v.z, v.z));
        ca1s[j] = ca1; ca2s[j] = ca2;
        m1 = fmaxf(m1, ca1); m2 = fmaxf(m2, ca2);
    }
    for (int off = 16; off; off >>= 1) {
        m1 = fmaxf(m1, __shfl_down_sync(m, m1, off));
        m2 = fmaxf(m2, __shfl_down_sync(m, m2, off));
    }
    if (lane == 0) { redf[w] = m1; redf[32 + w] = m2; }
    __syncthreads();
    if (tid == 0) {
        float a = redf[0], b = redf[32];
        for (int i = 1; i < 8; i++) { a = fmaxf(a, redf[i]); b = fmaxf(b, redf[32 + i]); }
        redf[0] = a; redf[32] = b;
    }
    __syncthreads();
    const float max1 = redf[0], max2 = redf[32];

    double ss = 0.0;
    for (int j = tid; j < K_BINS; j += 256) {
        float p1 = __fdiv_rn(ca1s[j], max1);
        float p2 = __fdiv_rn(ca2s[j], max2);
        double d = (double)p1 - (double)p2;
        ss += d * d;
    }
    for (int off = 16; off; off >>= 1) ss += __shfl_down_sync(m, ss, off);
    if (lane == 0) redd[w] = ss;
    __syncthreads();
    if (tid == 0) {
        double t = 0.0;
        for (int i = 0; i < 8; i++) t += redd[i];
        float loss = (float)sqrt(t);
        out[0] = __fdiv_rn(1.0f, loss + 1e-8f);
    }
}

// ---------------------------------------------------------------------------
// Inputs (metadata order): preds f32[60000], labels f32[60000], Fs i32[1],
//                          bpm_range f32[1400]. Output: f32[1].
// ---------------------------------------------------------------------------
extern "C" void kernel_launch(void* const* d_in, const int* in_sizes, int n_in,
                              void* d_out, int out_size) {
    const float* preds  = (const float*)d_in[0];
    const float* labels = (const float*)d_in[1];
    const float* bpm    = (const float*)d_in[3];

    prep_kernel<<<(N_SAMP / 2 + 255) / 256, 256>>>(preds, labels);
    psd_kernel<<<K_BINS / 2, BT>>>(bpm);
    final_kernel<<<1, 256>>>((float*)d_out);
}

// round 5
// speedup vs baseline: 1.1333x; 1.0433x over previous
#include <cuda_runtime.h>
#include <math.h>

#define N_SAMP 60000
#define NB1    118            // outer iterations
#define STRIDE 512            // n = STRIDE*n1 + 2*tid + {0,1}
#define N_PAD  (NB1 * STRIDE) // 60416, zero-padded tail
#define K_BINS 1400
#define BT     256
#define GRID_PSD (K_BINS / 2) // 700 blocks, 2 bins each

// Scratch (no allocations allowed)
__device__ float    g_ox[N_PAD];
__device__ float    g_oy[N_PAD];
__device__ float4   g_ri[K_BINS];   // (re1, im1, re2, im2)
__device__ unsigned g_ctr = 0;

// ---------------- packed f32x2 helpers (Blackwell native) ----------------
typedef unsigned long long ull;
__device__ __forceinline__ ull pk(float lo, float hi) {
    ull r; asm("mov.b64 %0,{%1,%2};" : "=l"(r) : "f"(lo), "f"(hi)); return r;
}
__device__ __forceinline__ void upk(ull v, float& lo, float& hi) {
    asm("mov.b64 {%0,%1},%2;" : "=f"(lo), "=f"(hi) : "l"(v));
}
__device__ __forceinline__ ull fma2(ull a, ull b, ull c) {
    ull d; asm("fma.rn.f32x2 %0,%1,%2,%3;" : "=l"(d) : "l"(a), "l"(b), "l"(c)); return d;
}
__device__ __forceinline__ ull mul2(ull a, ull b) {
    ull d; asm("mul.rn.f32x2 %0,%1,%2;" : "=l"(d) : "l"(a), "l"(b)); return d;
}
__device__ __forceinline__ ull add2(ull a, ull b) {
    ull d; asm("add.rn.f32x2 %0,%1,%2;" : "=l"(d) : "l"(a), "l"(b)); return d;
}
__device__ __forceinline__ ull neg2(ull a) {   // 2x LOP on alu pipe
    return a ^ 0x8000000080000000ULL;
}

// ---------------------------------------------------------------------------
// Kernel A: windowed signals into separate x/y arrays (for pair-aligned LDG),
// Hann symmetry halves the fp64 cos count. Proven-cheap structure from R2.
// ---------------------------------------------------------------------------
__global__ void prep_kernel(const float* __restrict__ preds,
                            const float* __restrict__ labels) {
    int i = blockIdx.x * blockDim.x + threadIdx.x;
    if (i < (N_PAD - N_SAMP)) { g_ox[N_SAMP + i] = 0.f; g_oy[N_SAMP + i] = 0.f; }
    if (i >= N_SAMP / 2) return;
    double t = 3.141592653589793 *
               ((double)(2 * i + 1 - N_SAMP) / (double)(N_SAMP - 1));
    float h = (float)(0.5 + 0.5 * cos(t));
    g_ox[i] = preds[i] * h;
    g_oy[i] = labels[i] * h;
    int m = N_SAMP - 1 - i;
    g_ox[m] = preds[m] * h;
    g_oy[m] = labels[m] * h;
}

// ---------------------------------------------------------------------------
// Kernel B: 2 bins per block, 2 consecutive n per lane (packed across n).
// Per-term math bitwise-identical to the proven R2 scheme:
//   tpn = RN(cF*n); e1,e2 exact FMA residuals; D = RN(k*e1+e2); ang = A - D
//   cos/sin(A) via table angle addition; first-order rotation by D.
// 29 packed FMA-pipe ops per iteration covering 4 (bin,n) terms.
// Last block (atomic counter) computes the final scalar inline.
// ---------------------------------------------------------------------------
__global__ void __launch_bounds__(BT)
psd_kernel(const float* __restrict__ bpm, float* __restrict__ out) {
    const int j0  = blockIdx.x * 2;
    const int tid = threadIdx.x;

    __shared__ float4 tbl[2][NB1];    // per bin: (cB, cB, -sB, -sB)
    __shared__ float4 wsum[8][2];
    // final-phase storage (only last block uses)
    __shared__ float  ca1s[K_BINS];
    __shared__ float  ca2s[K_BINS];
    __shared__ float  redf[64];
    __shared__ double redd[8];
    __shared__ unsigned done;

    const float cF   = (float)(2.0 * 3.141592653589793 / 60000.0);
    const float unit = (float)(30.0 / 60000.0);

    float  kk[2];
    double kc[2];
#pragma unroll
    for (int b = 0; b < 2; b++) {
        kk[b] = __fdiv_rn(__fdiv_rn(bpm[j0 + b], 60.0f), unit);
        kc[b] = (double)kk[b] * (double)cF;        // exact product in fp64
    }
    ull k2[2], nk2[2];
#pragma unroll
    for (int b = 0; b < 2; b++) {
        k2[b]  = pk(kk[b], kk[b]);
        nk2[b] = neg2(k2[b]);
    }

    // Block tables: cos/sin(k*cF*STRIDE*n1), duplicated lanes, negated sin
    for (int idx = tid; idx < 2 * NB1; idx += BT) {
        int b = (idx >= NB1) ? 1 : 0;
        int n1 = idx - b * NB1;
        double s, c;
        sincos(kc[b] * (double)(n1 * STRIDE), &s, &c);
        tbl[b][n1] = make_float4((float)c, (float)c, (float)(-s), (float)(-s));
    }

    // Per-thread inner factors: cos/sin(k*cF*(2*tid+q)), q in {0,1}
    ull cS2[2], sS2[2], ncS2[2];
#pragma unroll
    for (int b = 0; b < 2; b++) {
        double s0, c0, s1, c1;
        sincos(kc[b] * (double)(2 * tid),     &s0, &c0);
        sincos(kc[b] * (double)(2 * tid + 1), &s1, &c1);
        cS2[b]  = pk((float)c0, (float)c1);
        sS2[b]  = pk((float)s0, (float)s1);
        ncS2[b] = neg2(cS2[b]);
    }
    __syncthreads();

    // Main loop
    const ull cF2  = pk(cF, cF);
    const ull ncF2 = neg2(cF2);
    const ull stp2 = pk((float)STRIDE, (float)STRIDE);
    ull nf2 = pk((float)(2 * tid), (float)(2 * tid + 1));  // exact ints in f32
    ull aR[2] = {0ULL, 0ULL}, aI[2] = {0ULL, 0ULL};
    ull bR[2] = {0ULL, 0ULL}, bI[2] = {0ULL, 0ULL};
    const float* px = g_ox + 2 * tid;
    const float* py = g_oy + 2 * tid;

#pragma unroll 2
    for (int n1 = 0; n1 < NB1; ++n1) {
        // shared chain (both bins): reference rounding + exact residual
        ull tpn2 = mul2(cF2, nf2);               // RN(cF*n) per lane
        ull ne1  = fma2(ncF2, nf2, tpn2);        // = -(cF*n - tpn), exact
        nf2 = add2(nf2, stp2);
        ull ox2 = *(const ull*)(px + n1 * STRIDE);   // (o_x[n], o_x[n+1])
        ull oy2 = *(const ull*)(py + n1 * STRIDE);
#pragma unroll
        for (int b = 0; b < 2; b++) {
            float4 t = tbl[b][n1];               // LDS.128, aligned pairs
            ull cB2  = pk(t.x, t.y);
            ull nsB2 = pk(t.z, t.w);
            ull ang  = mul2(k2[b], tpn2);        // RN(k*tpn)
            ull ne2  = fma2(nk2[b], tpn2, ang);  // = -(k*tpn - ang), exact
            ull nD   = fma2(k2[b], ne1, ne2);    // = -D
            ull D    = neg2(nD);                 // ALU pipe
            ull cA   = fma2(nsB2, sS2[b], mul2(cB2, cS2[b]));
            ull sA   = fma2(cB2, sS2[b], mul2(nsB2, ncS2[b]));
            ull cr   = fma2(D, sA, cA);          // cos(A - D), 1st order
            ull sr   = fma2(nD, cA, sA);         // sin(A - D), 1st order
            aR[b] = fma2(cr, ox2, aR[b]);
            aI[b] = fma2(sr, ox2, aI[b]);
            bR[b] = fma2(cr, oy2, bR[b]);
            bI[b] = fma2(sr, oy2, bI[b]);
        }
    }

    // Reduce: combine packed halves, then warp/block tree (8 scalars)
    float r1[2], i1[2], r2[2], i2[2];
#pragma unroll
    for (int b = 0; b < 2; b++) {
        float lo, hi;
        upk(aR[b], lo, hi); r1[b] = lo + hi;
        upk(aI[b], lo, hi); i1[b] = lo + hi;
        upk(bR[b], lo, hi); r2[b] = lo + hi;
        upk(bI[b], lo, hi); i2[b] = lo + hi;
    }
    const unsigned msk = 0xFFFFFFFFu;
    for (int off = 16; off; off >>= 1) {
#pragma unroll
        for (int b = 0; b < 2; b++) {
            r1[b] += __shfl_down_sync(msk, r1[b], off);
            i1[b] += __shfl_down_sync(msk, i1[b], off);
            r2[b] += __shfl_down_sync(msk, r2[b], off);
            i2[b] += __shfl_down_sync(msk, i2[b], off);
        }
    }
    int w = tid >> 5, lane = tid & 31;
    if (lane == 0) {
#pragma unroll
        for (int b = 0; b < 2; b++)
            wsum[w][b] = make_float4(r1[b], i1[b], r2[b], i2[b]);
    }
    __syncthreads();
    if (w == 0) {
#pragma unroll
        for (int b = 0; b < 2; b++) {
            float4 v = (lane < 8) ? wsum[lane][b] : make_float4(0.f, 0.f, 0.f, 0.f);
            for (int off = 4; off; off >>= 1) {
                v.x += __shfl_down_sync(msk, v.x, off);
                v.y += __shfl_down_sync(msk, v.y, off);
                v.z += __shfl_down_sync(msk, v.z, off);
                v.w += __shfl_down_sync(msk, v.w, off);
            }
            if (lane == 0) g_ri[j0 + b] = v;
        }
    }

    // ---- completion protocol: last block computes the final scalar ----
    __threadfence();
    if (tid == 0) done = atomicAdd(&g_ctr, 1);
    __syncthreads();
    if (done != GRID_PSD - 1) return;
    __threadfence();   // order: counter observation -> g_ri reads

    // Final reduction (proven R2 logic): pn = ca/max(ca); ||pn1-pn2||; 1/(l+eps)
    float m1 = 0.f, m2 = 0.f;
    for (int j = tid; j < K_BINS; j += BT) {
        float4 v = g_ri[j];
        float ca1 = __fmaf_rn(v.y, v.y, __fmul_rn(v.x, v.x));
        float ca2 = __fmaf_rn(v.w, v.w, __fmul_rn(v.z, v.z));
        ca1s[j] = ca1; ca2s[j] = ca2;
        m1 = fmaxf(m1, ca1); m2 = fmaxf(m2, ca2);
    }
    for (int off = 16; off; off >>= 1) {
        m1 = fmaxf(m1, __shfl_down_sync(msk, m1, off));
        m2 = fmaxf(m2, __shfl_down_sync(msk, m2, off));
    }
    if (lane == 0) { redf[w] = m1; redf[32 + w] = m2; }
    __syncthreads();
    if (tid == 0) {
        float a = redf[0], bb = redf[32];
        for (int i = 1; i < 8; i++) { a = fmaxf(a, redf[i]); bb = fmaxf(bb, redf[32 + i]); }
        redf[0] = a; redf[32] = bb;
    }
    __syncthreads();
    const float max1 = redf[0], max2 = redf[32];

    double ss = 0.0;
    for (int j = tid; j < K_BINS; j += BT) {
        float p1 = __fdiv_rn(ca1s[j], max1);
        float p2 = __fdiv_rn(ca2s[j], max2);
        double d = (double)p1 - (double)p2;
        ss += d * d;
    }
    for (int off = 16; off; off >>= 1) ss += __shfl_down_sync(msk, ss, off);
    if (lane == 0) redd[w] = ss;
    __syncthreads();
    if (tid == 0) {
        double t = 0.0;
        for (int i = 0; i < 8; i++) t += redd[i];
        float loss = (float)sqrt(t);
        out[0] = __fdiv_rn(1.0f, loss + 1e-8f);
        g_ctr = 0;     // reset for next graph replay
    }
}

// ---------------------------------------------------------------------------
// Inputs (metadata order): preds f32[60000], labels f32[60000], Fs i32[1],
//                          bpm_range f32[1400]. Output: f32[1].
// ---------------------------------------------------------------------------
extern "C" void kernel_launch(void* const* d_in, const int* in_sizes, int n_in,
                              void* d_out, int out_size) {
    const float* preds  = (const float*)d_in[0];
    const float* labels = (const float*)d_in[1];
    const float* bpm    = (const float*)d_in[3];

    prep_kernel<<<(N_SAMP / 2 + 255) / 256, 256>>>(preds, labels);
    psd_kernel<<<GRID_PSD, BT>>>(bpm, (float*)d_out);
}